// round 1
// baseline (speedup 1.0000x reference)
#include <cuda_runtime.h>
#include <math.h>

#define NROWS 8192
#define HALF_N 4096
#define DIM 512
#define BM 128
#define BN 128
#define BK 16
#define NTILES (NROWS / BN)   // 64

// Scratch (allocation-free rule: __device__ globals)
__device__ float g_unit[NROWS * DIM];        // normalized feats, 16 MB
__device__ float g_part[NTILES * NROWS];     // per-(coltile,row) exp partial sums, 2 MB
__device__ float g_pos[NROWS];               // positive logit per row

// ---------------------------------------------------------------------------
// 1) Normalize: one block (128 threads) per row of concat(z1, z2)
// ---------------------------------------------------------------------------
__global__ __launch_bounds__(128)
void normalize_kernel(const float* __restrict__ z1, const float* __restrict__ z2) {
    int row = blockIdx.x;
    int t = threadIdx.x;
    const float* src = (row < HALF_N) ? (z1 + (size_t)row * DIM)
                                      : (z2 + (size_t)(row - HALF_N) * DIM);
    float v[4];
    float ss = 0.f;
#pragma unroll
    for (int i = 0; i < 4; i++) {
        v[i] = src[t + i * 128];
        ss += v[i] * v[i];
    }
#pragma unroll
    for (int o = 16; o > 0; o >>= 1) ss += __shfl_xor_sync(0xffffffffu, ss, o);
    __shared__ float ws[4];
    if ((t & 31) == 0) ws[t >> 5] = ss;
    __syncthreads();
    float tot = ws[0] + ws[1] + ws[2] + ws[3];
    float inv = 1.0f / fmaxf(sqrtf(tot), 1e-8f);
#pragma unroll
    for (int i = 0; i < 4; i++)
        g_unit[(size_t)row * DIM + t + i * 128] = v[i] * inv;
}

// ---------------------------------------------------------------------------
// 2) Fused S = U*U^T tile GEMM + exp row-sum + positive capture.
//    128x128 tile per block, 256 threads, 8x8 per thread, BK=16.
//    Diagonal (j==i) skipped (reference masks it to -9e15 -> exp = 0).
//    Row partials written to g_part[bj][row]  (unique writer -> deterministic).
// ---------------------------------------------------------------------------
__global__ __launch_bounds__(256)
void gemm_exp_kernel() {
    int bj = blockIdx.x;           // column tile
    int bi = blockIdx.y;           // row tile
    int R0 = bi * BM, C0 = bj * BN;

    __shared__ float As[BK][BM + 4];   // k-major, padded
    __shared__ float Bs[BK][BN + 4];

    int t = threadIdx.x;
    int tx = t & 15;               // -> 8 columns
    int ty = t >> 4;               // -> 8 rows

    float acc[8][8];
#pragma unroll
    for (int i = 0; i < 8; i++)
#pragma unroll
        for (int j = 0; j < 8; j++) acc[i][j] = 0.f;

    for (int kk = 0; kk < DIM; kk += BK) {
        // Each thread loads 2 float4 per operand tile (512 float4 / operand)
#pragma unroll
        for (int l = 0; l < 2; l++) {
            int idx = t * 2 + l;       // 0..511
            int r   = idx >> 2;        // row within tile 0..127
            int kq  = idx & 3;         // which float4 along k
            float4 a = *(const float4*)&g_unit[(size_t)(R0 + r) * DIM + kk + kq * 4];
            As[kq * 4 + 0][r] = a.x; As[kq * 4 + 1][r] = a.y;
            As[kq * 4 + 2][r] = a.z; As[kq * 4 + 3][r] = a.w;
            float4 b = *(const float4*)&g_unit[(size_t)(C0 + r) * DIM + kk + kq * 4];
            Bs[kq * 4 + 0][r] = b.x; Bs[kq * 4 + 1][r] = b.y;
            Bs[kq * 4 + 2][r] = b.z; Bs[kq * 4 + 3][r] = b.w;
        }
        __syncthreads();
#pragma unroll
        for (int k = 0; k < BK; k++) {
            float a[8], b[8];
#pragma unroll
            for (int i = 0; i < 8; i++) a[i] = As[k][ty * 8 + i];
#pragma unroll
            for (int j = 0; j < 8; j++) b[j] = Bs[k][tx * 8 + j];
#pragma unroll
            for (int i = 0; i < 8; i++)
#pragma unroll
                for (int j = 0; j < 8; j++)
                    acc[i][j] = fmaf(a[i], b[j], acc[i][j]);
        }
        __syncthreads();
    }

    // Epilogue: logits = 10 * cos; exp row-sum (skip diagonal), capture positive.
    float part[8];
#pragma unroll
    for (int i = 0; i < 8; i++) {
        int rg = R0 + ty * 8 + i;
        int pcol = (rg + HALF_N) & (NROWS - 1);
        float s = 0.f;
#pragma unroll
        for (int j = 0; j < 8; j++) {
            int cg = C0 + tx * 8 + j;
            float logit = acc[i][j] * 10.0f;
            if (cg == pcol) g_pos[rg] = logit;      // unique writer per row
            s += (cg == rg) ? 0.f : __expf(logit);
        }
        part[i] = s;
    }

    // Reduce 16 column-partials per local row in smem (reuse As; all reads of
    // As/Bs completed before the loop-ending __syncthreads above).
    float* red = &As[0][0];        // needs 128*16 = 2048 floats (<= 16*132)
#pragma unroll
    for (int i = 0; i < 8; i++)
        red[(ty * 8 + i) * 16 + tx] = part[i];
    __syncthreads();
    if (t < BM) {
        float s = 0.f;
#pragma unroll
        for (int c = 0; c < 16; c++) s += red[t * 16 + c];
        g_part[(size_t)bj * NROWS + R0 + t] = s;
    }
}

// ---------------------------------------------------------------------------
// 3) Finalize: mean over rows of (-pos + log(sum exp)). No max-shift needed:
//    logits in [-10, 10], row sum <= 8191*e^10 fits fp32 comfortably.
// ---------------------------------------------------------------------------
__global__ __launch_bounds__(256)
void finalize_kernel(float* __restrict__ out) {
    int t = threadIdx.x;
    float sum = 0.f;
    for (int r = t; r < NROWS; r += 256) {
        float rs = 0.f;
        for (int c = 0; c < NTILES; c++) rs += g_part[(size_t)c * NROWS + r];
        sum += logf(rs) - g_pos[r];
    }
#pragma unroll
    for (int o = 16; o > 0; o >>= 1) sum += __shfl_xor_sync(0xffffffffu, sum, o);
    __shared__ float ws[8];
    if ((t & 31) == 0) ws[t >> 5] = sum;
    __syncthreads();
    if (t == 0) {
        float s = 0.f;
#pragma unroll
        for (int w = 0; w < 8; w++) s += ws[w];
        out[0] = s / (float)NROWS;
    }
}

extern "C" void kernel_launch(void* const* d_in, const int* in_sizes, int n_in,
                              void* d_out, int out_size) {
    const float* z1 = (const float*)d_in[0];
    const float* z2 = (const float*)d_in[1];

    normalize_kernel<<<NROWS, 128>>>(z1, z2);
    dim3 grid(NTILES, NTILES);
    gemm_exp_kernel<<<grid, 256>>>();
    finalize_kernel<<<1, 256>>>((float*)d_out);
}

// round 3
// speedup vs baseline: 7.0087x; 7.0087x over previous
#include <cuda_runtime.h>
#include <cuda_bf16.h>
#include <math.h>
#include <stdint.h>

#define NROWS 8192
#define HALF_N 4096
#define DIM 512
#define NT 64                     // 8192/128 tiles per dim
#define PITCH 40                  // smem row pitch in bf16 elems (32 data + 8 pad) = 80B
#define TILE_B (128 * PITCH * 2)  // 10240 B per operand tile
#define STAGE_B (2 * TILE_B)      // 20480 B per stage (A+B)

// ---------------- device scratch (allocation-free rule) ----------------
__device__ __align__(256) __nv_bfloat16 g_unitb[NROWS * DIM]; // 8 MB normalized bf16
__device__ float g_part[NT * NROWS];                          // per-(coltile,row) partials
__device__ float g_pos[NROWS];
__device__ float g_row[NROWS];

__device__ __forceinline__ uint32_t smem_u32(const void* p) {
    uint32_t a;
    asm("{ .reg .u64 t; cvta.to.shared.u64 t, %1; cvt.u32.u64 %0, t; }"
        : "=r"(a) : "l"(p));
    return a;
}

#define CP_ASYNC16(dst, src) \
    asm volatile("cp.async.cg.shared.global [%0], [%1], 16;" :: "r"(dst), "l"(src))
#define CP_COMMIT() asm volatile("cp.async.commit_group;" ::: "memory")
#define CP_WAIT0()  asm volatile("cp.async.wait_group 0;" ::: "memory")

#define LDMATRIX_X4(r0, r1, r2, r3, addr) \
    asm volatile("ldmatrix.sync.aligned.m8n8.x4.shared.b16 {%0,%1,%2,%3}, [%4];" \
                 : "=r"(r0), "=r"(r1), "=r"(r2), "=r"(r3) : "r"(addr))

#define MMA_BF16(c, a, b0, b1) \
    asm volatile("mma.sync.aligned.m16n8k16.row.col.f32.bf16.bf16.f32 " \
                 "{%0,%1,%2,%3}, {%4,%5,%6,%7}, {%8,%9}, {%0,%1,%2,%3};" \
                 : "+f"((c)[0]), "+f"((c)[1]), "+f"((c)[2]), "+f"((c)[3]) \
                 : "r"((a)[0]), "r"((a)[1]), "r"((a)[2]), "r"((a)[3]), \
                   "r"(b0), "r"(b1))

// ---------------------------------------------------------------------------
// 1) Normalize + bf16 convert: one block (128 threads) per row of concat(z1,z2)
// ---------------------------------------------------------------------------
__global__ __launch_bounds__(128)
void normalize_kernel(const float* __restrict__ z1, const float* __restrict__ z2) {
    int row = blockIdx.x;
    int t = threadIdx.x;
    const float* src = (row < HALF_N) ? (z1 + (size_t)row * DIM)
                                      : (z2 + (size_t)(row - HALF_N) * DIM);
    float v[4];
    float ss = 0.f;
#pragma unroll
    for (int i = 0; i < 4; i++) {
        v[i] = src[t + i * 128];
        ss += v[i] * v[i];
    }
#pragma unroll
    for (int o = 16; o > 0; o >>= 1) ss += __shfl_xor_sync(0xffffffffu, ss, o);
    __shared__ float ws[4];
    if ((t & 31) == 0) ws[t >> 5] = ss;
    __syncthreads();
    float tot = ws[0] + ws[1] + ws[2] + ws[3];
    float inv = 1.0f / fmaxf(sqrtf(tot), 1e-8f);
#pragma unroll
    for (int i = 0; i < 4; i++)
        g_unitb[(size_t)row * DIM + t + i * 128] = __float2bfloat16(v[i] * inv);
}

// ---------------------------------------------------------------------------
// 2) bf16 HMMA GEMM tile (128x128, K=512, BK=32, 2-stage cp.async) +
//    fused exp row-sum epilogue (register accumulators).
//    8 warps: warp_m = wid&1 (2 x 64 rows), warp_n = wid>>1 (4 x 32 cols).
// ---------------------------------------------------------------------------
__device__ __forceinline__ void load_stage(uint32_t sbase,
                                           const __nv_bfloat16* __restrict__ g,
                                           int R0, int C0, int kk, int t) {
#pragma unroll
    for (int l = 0; l < 2; l++) {          // A tile: 512 x 16B chunks
        int idx = t + l * 256;
        int row = idx >> 2, c4 = idx & 3;
        uint32_t dst = sbase + (uint32_t)(row * 80 + c4 * 16);
        const void* src = g + (size_t)(R0 + row) * DIM + kk + c4 * 8;
        CP_ASYNC16(dst, src);
    }
#pragma unroll
    for (int l = 0; l < 2; l++) {          // B tile
        int idx = t + l * 256;
        int row = idx >> 2, c4 = idx & 3;
        uint32_t dst = sbase + (uint32_t)(TILE_B + row * 80 + c4 * 16);
        const void* src = g + (size_t)(C0 + row) * DIM + kk + c4 * 8;
        CP_ASYNC16(dst, src);
    }
}

__global__ __launch_bounds__(256, 2)
void gemm_exp_kernel() {
    __shared__ __align__(128) char sm[2 * STAGE_B];   // 40960 B
    uint32_t sb = smem_u32(sm);

    int t = threadIdx.x;
    int lane = t & 31, wid = t >> 5;
    int warp_m = wid & 1, warp_n = wid >> 1;
    int bj = blockIdx.x, bi = blockIdx.y;
    int R0 = bi * 128, C0 = bj * 128;

    float acc[4][4][4];
#pragma unroll
    for (int i = 0; i < 4; i++)
#pragma unroll
        for (int f = 0; f < 4; f++)
#pragma unroll
            for (int e = 0; e < 4; e++) acc[i][f][e] = 0.f;

    // fragment load address components (per thread, stage-relative)
    int a_row = warp_m * 64 + (lane & 7) + ((lane >> 3) & 1) * 8; // + i*16
    int a_col8 = (lane >> 4) * 8;                                 // + k0
    int b_row = warp_n * 32 + (lane & 7) + (lane >> 4) * 8;       // + nb*16
    int b_col8 = ((lane >> 3) & 1) * 8;                           // + k0

    load_stage(sb, g_unitb, R0, C0, 0, t);
    CP_COMMIT();

#pragma unroll 1
    for (int it = 0; it < 16; it++) {
        CP_WAIT0();
        __syncthreads();
        if (it < 15) {
            load_stage(sb + ((it + 1) & 1) * STAGE_B, g_unitb, R0, C0,
                       (it + 1) * 32, t);
            CP_COMMIT();
        }
        uint32_t ab = sb + (it & 1) * STAGE_B;
        uint32_t bb = ab + TILE_B;

#pragma unroll
        for (int ks = 0; ks < 2; ks++) {
            int k0 = ks * 16;
            uint32_t a[4][4], b[2][4];
#pragma unroll
            for (int i = 0; i < 4; i++) {
                uint32_t addr = ab + (uint32_t)((a_row + i * 16) * 80 +
                                                (a_col8 + k0) * 2);
                LDMATRIX_X4(a[i][0], a[i][1], a[i][2], a[i][3], addr);
            }
#pragma unroll
            for (int nb = 0; nb < 2; nb++) {
                uint32_t addr = bb + (uint32_t)((b_row + nb * 16) * 80 +
                                                (b_col8 + k0) * 2);
                LDMATRIX_X4(b[nb][0], b[nb][1], b[nb][2], b[nb][3], addr);
            }
#pragma unroll
            for (int i = 0; i < 4; i++)
#pragma unroll
                for (int f = 0; f < 4; f++)
                    MMA_BF16(acc[i][f], a[i], b[f >> 1][(f & 1) * 2],
                             b[f >> 1][(f & 1) * 2 + 1]);
        }
    }
    __syncthreads();   // all compute done; smem now reusable for reduction

    // Epilogue. C frag layout: reg e -> row (lane>>2) + 8*(e>>1), col 2*(lane&3)+(e&1)
    int g = lane >> 2, tq = lane & 3;
    float* red = (float*)sm;                 // 128 rows x 4 warp_n = 2 KB
    float rsum[4][2];
#pragma unroll
    for (int i = 0; i < 4; i++) { rsum[i][0] = 0.f; rsum[i][1] = 0.f; }

#pragma unroll
    for (int i = 0; i < 4; i++) {
#pragma unroll
        for (int h = 0; h < 2; h++) {
            int rg = R0 + warp_m * 64 + i * 16 + g + 8 * h;
            int pcol = (rg + HALF_N) & (NROWS - 1);
            float s = 0.f;
#pragma unroll
            for (int f = 0; f < 4; f++) {
#pragma unroll
                for (int e = 0; e < 2; e++) {
                    int cg = C0 + warp_n * 32 + f * 8 + tq * 2 + e;
                    float logit = acc[i][f][h * 2 + e] * 10.0f;
                    if (cg == pcol) g_pos[rg] = logit;         // unique writer
                    s += (cg == rg) ? 0.f : __expf(logit);     // diag masked
                }
            }
            rsum[i][h] = s;
        }
    }
#pragma unroll
    for (int i = 0; i < 4; i++)
#pragma unroll
        for (int h = 0; h < 2; h++) {
            float v = rsum[i][h];
            v += __shfl_xor_sync(0xffffffffu, v, 1);
            v += __shfl_xor_sync(0xffffffffu, v, 2);
            if (tq == 0)
                red[(warp_m * 64 + i * 16 + g + 8 * h) * 4 + warp_n] = v;
        }
    __syncthreads();
    if (t < 128) {
        float s = red[t * 4] + red[t * 4 + 1] + red[t * 4 + 2] + red[t * 4 + 3];
        g_part[(size_t)bj * NROWS + R0 + t] = s;
    }
}

// ---------------------------------------------------------------------------
// 3) Finalize (two deterministic stages)
// ---------------------------------------------------------------------------
__global__ __launch_bounds__(128)
void finalize1_kernel() {
    int r = blockIdx.x * 128 + threadIdx.x;
    float rs = 0.f;
#pragma unroll 8
    for (int c = 0; c < NT; c++) rs += g_part[(size_t)c * NROWS + r];
    g_row[r] = logf(rs) - g_pos[r];
}

__global__ __launch_bounds__(256)
void finalize2_kernel(float* __restrict__ out) {
    int t = threadIdx.x;
    float sum = 0.f;
    for (int r = t; r < NROWS; r += 256) sum += g_row[r];
#pragma unroll
    for (int o = 16; o > 0; o >>= 1) sum += __shfl_xor_sync(0xffffffffu, sum, o);
    __shared__ float ws[8];
    if ((t & 31) == 0) ws[t >> 5] = sum;
    __syncthreads();
    if (t == 0) {
        float s = 0.f;
#pragma unroll
        for (int w = 0; w < 8; w++) s += ws[w];
        out[0] = s / (float)NROWS;
    }
}

extern "C" void kernel_launch(void* const* d_in, const int* in_sizes, int n_in,
                              void* d_out, int out_size) {
    const float* z1 = (const float*)d_in[0];
    const float* z2 = (const float*)d_in[1];

    normalize_kernel<<<NROWS, 128>>>(z1, z2);
    dim3 grid(NT, NT);
    gemm_exp_kernel<<<grid, 256>>>();
    finalize1_kernel<<<NT, 128>>>();
    finalize2_kernel<<<1, 256>>>((float*)d_out);
}

// round 4
// speedup vs baseline: 12.2347x; 1.7456x over previous
#include <cuda_runtime.h>
#include <cuda_bf16.h>
#include <math.h>
#include <stdint.h>

#define NROWS 8192
#define HALF_N 4096
#define DIM 512
#define NT 64                     // 8192/128 tiles per dim
#define PITCH 40                  // smem row pitch in bf16 elems (32 data + 8 pad) = 80B
#define TILE_B (128 * PITCH * 2)  // 10240 B per operand tile
#define STAGE_B (2 * TILE_B)      // 20480 B per stage (A+B)

// ---------------- device scratch (allocation-free rule) ----------------
__device__ __align__(256) __nv_bfloat16 g_unitb[NROWS * DIM]; // 8 MB normalized bf16
__device__ float g_part[NT * NROWS];                          // per-(slot,row) partials
__device__ float g_pos[NROWS];
__device__ float g_row[NROWS];

__device__ __forceinline__ uint32_t smem_u32(const void* p) {
    uint32_t a;
    asm("{ .reg .u64 t; cvta.to.shared.u64 t, %1; cvt.u32.u64 %0, t; }"
        : "=r"(a) : "l"(p));
    return a;
}

#define CP_ASYNC16(dst, src) \
    asm volatile("cp.async.cg.shared.global [%0], [%1], 16;" :: "r"(dst), "l"(src))
#define CP_COMMIT() asm volatile("cp.async.commit_group;" ::: "memory")
#define CP_WAIT0()  asm volatile("cp.async.wait_group 0;" ::: "memory")

#define LDMATRIX_X4(r0, r1, r2, r3, addr) \
    asm volatile("ldmatrix.sync.aligned.m8n8.x4.shared.b16 {%0,%1,%2,%3}, [%4];" \
                 : "=r"(r0), "=r"(r1), "=r"(r2), "=r"(r3) : "r"(addr))

#define MMA_BF16(c, a, b0, b1) \
    asm volatile("mma.sync.aligned.m16n8k16.row.col.f32.bf16.bf16.f32 " \
                 "{%0,%1,%2,%3}, {%4,%5,%6,%7}, {%8,%9}, {%0,%1,%2,%3};" \
                 : "+f"((c)[0]), "+f"((c)[1]), "+f"((c)[2]), "+f"((c)[3]) \
                 : "r"((a)[0]), "r"((a)[1]), "r"((a)[2]), "r"((a)[3]), \
                   "r"(b0), "r"(b1))

// ---------------------------------------------------------------------------
// 1) Normalize + bf16 convert: one block (128 threads) per row of concat(z1,z2)
// ---------------------------------------------------------------------------
__global__ __launch_bounds__(128)
void normalize_kernel(const float* __restrict__ z1, const float* __restrict__ z2) {
    int row = blockIdx.x;
    int t = threadIdx.x;
    const float* src = (row < HALF_N) ? (z1 + (size_t)row * DIM)
                                      : (z2 + (size_t)(row - HALF_N) * DIM);
    float v[4];
    float ss = 0.f;
#pragma unroll
    for (int i = 0; i < 4; i++) {
        v[i] = src[t + i * 128];
        ss += v[i] * v[i];
    }
#pragma unroll
    for (int o = 16; o > 0; o >>= 1) ss += __shfl_xor_sync(0xffffffffu, ss, o);
    __shared__ float ws[4];
    if ((t & 31) == 0) ws[t >> 5] = ss;
    __syncthreads();
    float tot = ws[0] + ws[1] + ws[2] + ws[3];
    float inv = 1.0f / fmaxf(sqrtf(tot), 1e-8f);
#pragma unroll
    for (int i = 0; i < 4; i++)
        g_unitb[(size_t)row * DIM + t + i * 128] = __float2bfloat16(v[i] * inv);
}

// ---------------------------------------------------------------------------
// 2) bf16 HMMA GEMM tile (128x128, K=512, BK=32, 2-stage cp.async).
//    UPPER-TRIANGLE ONLY (bi <= bj): each off-diagonal tile emits BOTH
//    row-sum partials (rows of tile bi) and col-sum partials (rows of tile bj,
//    by symmetry S = S^T). Diagonal tiles emit row sums with diag masked.
//    8 warps: warp_m = wid&1 (2 x 64 rows), warp_n = wid>>1 (4 x 32 cols).
// ---------------------------------------------------------------------------
__device__ __forceinline__ void load_stage(uint32_t sbase,
                                           const __nv_bfloat16* __restrict__ g,
                                           int R0, int C0, int kk, int t) {
#pragma unroll
    for (int l = 0; l < 2; l++) {          // A tile: 512 x 16B chunks
        int idx = t + l * 256;
        int row = idx >> 2, c4 = idx & 3;
        uint32_t dst = sbase + (uint32_t)(row * 80 + c4 * 16);
        const void* src = g + (size_t)(R0 + row) * DIM + kk + c4 * 8;
        CP_ASYNC16(dst, src);
    }
#pragma unroll
    for (int l = 0; l < 2; l++) {          // B tile
        int idx = t + l * 256;
        int row = idx >> 2, c4 = idx & 3;
        uint32_t dst = sbase + (uint32_t)(TILE_B + row * 80 + c4 * 16);
        const void* src = g + (size_t)(C0 + row) * DIM + kk + c4 * 8;
        CP_ASYNC16(dst, src);
    }
}

__global__ __launch_bounds__(256, 2)
void gemm_exp_kernel() {
    int bj = blockIdx.x, bi = blockIdx.y;
    if (bi > bj) return;                    // upper triangle only

    __shared__ __align__(128) char sm[2 * STAGE_B];   // 40960 B
    uint32_t sb = smem_u32(sm);

    int t = threadIdx.x;
    int lane = t & 31, wid = t >> 5;
    int warp_m = wid & 1, warp_n = wid >> 1;
    int R0 = bi * 128, C0 = bj * 128;
    bool offdiag = (bi != bj);

    float acc[4][4][4];
#pragma unroll
    for (int i = 0; i < 4; i++)
#pragma unroll
        for (int f = 0; f < 4; f++)
#pragma unroll
            for (int e = 0; e < 4; e++) acc[i][f][e] = 0.f;

    // fragment load address components (per thread, stage-relative)
    int a_row = warp_m * 64 + (lane & 7) + ((lane >> 3) & 1) * 8; // + i*16
    int a_col8 = (lane >> 4) * 8;                                 // + k0
    int b_row = warp_n * 32 + (lane & 7) + (lane >> 4) * 8;       // + nb*16
    int b_col8 = ((lane >> 3) & 1) * 8;                           // + k0

    load_stage(sb, g_unitb, R0, C0, 0, t);
    CP_COMMIT();

#pragma unroll 1
    for (int it = 0; it < 16; it++) {
        CP_WAIT0();
        __syncthreads();
        if (it < 15) {
            load_stage(sb + ((it + 1) & 1) * STAGE_B, g_unitb, R0, C0,
                       (it + 1) * 32, t);
            CP_COMMIT();
        }
        uint32_t ab = sb + (it & 1) * STAGE_B;
        uint32_t bb = ab + TILE_B;

#pragma unroll
        for (int ks = 0; ks < 2; ks++) {
            int k0 = ks * 16;
            uint32_t a[4][4], b[2][4];
#pragma unroll
            for (int i = 0; i < 4; i++) {
                uint32_t addr = ab + (uint32_t)((a_row + i * 16) * 80 +
                                                (a_col8 + k0) * 2);
                LDMATRIX_X4(a[i][0], a[i][1], a[i][2], a[i][3], addr);
            }
#pragma unroll
            for (int nb = 0; nb < 2; nb++) {
                uint32_t addr = bb + (uint32_t)((b_row + nb * 16) * 80 +
                                                (b_col8 + k0) * 2);
                LDMATRIX_X4(b[nb][0], b[nb][1], b[nb][2], b[nb][3], addr);
            }
#pragma unroll
            for (int i = 0; i < 4; i++)
#pragma unroll
                for (int f = 0; f < 4; f++)
                    MMA_BF16(acc[i][f], a[i], b[f >> 1][(f & 1) * 2],
                             b[f >> 1][(f & 1) * 2 + 1]);
        }
    }
    __syncthreads();   // all compute done; smem now reusable for reduction

    // Epilogue. C frag: reg e -> row (lane>>2) + 8*(e>>1), col 2*(lane&3)+(e&1)
    int g = lane >> 2, tq = lane & 3;
    float* red  = (float*)sm;                // 128 rows x 4 warp_n   (2 KB)
    float* redC = (float*)(sm + 2048);       // 128 cols x 2 warp_m   (1 KB)
    float rsum[4][2];
    float csum[4][2];
#pragma unroll
    for (int f = 0; f < 4; f++) { csum[f][0] = 0.f; csum[f][1] = 0.f; }

#pragma unroll
    for (int i = 0; i < 4; i++) {
#pragma unroll
        for (int h = 0; h < 2; h++) {
            int rg = R0 + warp_m * 64 + i * 16 + g + 8 * h;
            int pcol = (rg + HALF_N) & (NROWS - 1);
            float s = 0.f;
#pragma unroll
            for (int f = 0; f < 4; f++) {
#pragma unroll
                for (int e = 0; e < 2; e++) {
                    int cg = C0 + warp_n * 32 + f * 8 + tq * 2 + e;
                    float logit = acc[i][f][h * 2 + e] * 10.0f;
                    if (cg == pcol) {          // only occurs when bj == bi+32
                        g_pos[rg] = logit;     // unique writers (symmetric pair)
                        g_pos[cg] = logit;
                    }
                    float ev = (cg == rg) ? 0.f : __expf(logit);
                    s += ev;
                    csum[f][e] += ev;
                }
            }
            rsum[i][h] = s;
        }
    }
    // row-sum reduction over the 4 column-quads within each warp
#pragma unroll
    for (int i = 0; i < 4; i++)
#pragma unroll
        for (int h = 0; h < 2; h++) {
            float v = rsum[i][h];
            v += __shfl_xor_sync(0xffffffffu, v, 1);
            v += __shfl_xor_sync(0xffffffffu, v, 2);
            if (tq == 0)
                red[(warp_m * 64 + i * 16 + g + 8 * h) * 4 + warp_n] = v;
        }
    // col-sum reduction over the 8 row-groups within each warp
    if (offdiag) {
#pragma unroll
        for (int f = 0; f < 4; f++)
#pragma unroll
            for (int e = 0; e < 2; e++) {
                float v = csum[f][e];
                v += __shfl_xor_sync(0xffffffffu, v, 4);
                v += __shfl_xor_sync(0xffffffffu, v, 8);
                v += __shfl_xor_sync(0xffffffffu, v, 16);
                if (g == 0)
                    redC[(warp_n * 32 + f * 8 + tq * 2 + e) * 2 + warp_m] = v;
            }
    }
    __syncthreads();
    if (t < 128) {
        float s = red[t * 4] + red[t * 4 + 1] + red[t * 4 + 2] + red[t * 4 + 3];
        g_part[(size_t)bj * NROWS + R0 + t] = s;              // rows of tile bi
        if (offdiag)
            g_part[(size_t)bi * NROWS + C0 + t] = redC[t * 2] + redC[t * 2 + 1];
    }
}

// ---------------------------------------------------------------------------
// 3) Finalize (two deterministic stages)
// ---------------------------------------------------------------------------
__global__ __launch_bounds__(128)
void finalize1_kernel() {
    int r = blockIdx.x * 128 + threadIdx.x;
    float rs = 0.f;
#pragma unroll 8
    for (int c = 0; c < NT; c++) rs += g_part[(size_t)c * NROWS + r];
    g_row[r] = logf(rs) - g_pos[r];
}

__global__ __launch_bounds__(1024)
void finalize2_kernel(float* __restrict__ out) {
    int t = threadIdx.x;
    float sum = 0.f;
    for (int r = t; r < NROWS; r += 1024) sum += g_row[r];
#pragma unroll
    for (int o = 16; o > 0; o >>= 1) sum += __shfl_xor_sync(0xffffffffu, sum, o);
    __shared__ float ws[32];
    if ((t & 31) == 0) ws[t >> 5] = sum;
    __syncthreads();
    if (t == 0) {
        float s = 0.f;
#pragma unroll
        for (int w = 0; w < 32; w++) s += ws[w];
        out[0] = s / (float)NROWS;
    }
}

extern "C" void kernel_launch(void* const* d_in, const int* in_sizes, int n_in,
                              void* d_out, int out_size) {
    const float* z1 = (const float*)d_in[0];
    const float* z2 = (const float*)d_in[1];

    normalize_kernel<<<NROWS, 128>>>(z1, z2);
    dim3 grid(NT, NT);
    gemm_exp_kernel<<<grid, 256>>>();
    finalize1_kernel<<<NT, 128>>>();
    finalize2_kernel<<<1, 1024>>>((float*)d_out);
}

// round 5
// speedup vs baseline: 13.1672x; 1.0762x over previous
#include <cuda_runtime.h>
#include <cuda_bf16.h>
#include <math.h>
#include <stdint.h>

#define NROWS 8192
#define HALF_N 4096
#define DIM 512
#define NT 64                     // 8192/128 tiles per dim
#define NTRI (NT * (NT + 1) / 2)  // 2080 upper-triangle tiles
#define BK 64
#define PITCHB 144                // smem row pitch bytes (64 bf16 = 128B + 16B pad)
#define TILE_B (128 * PITCHB)     // 18432 B per operand tile
#define STAGE_B (2 * TILE_B)      // 36864 B per stage (A+B)
#define SMEM_DYN (2 * STAGE_B)    // 73728 B

// ---------------- device scratch (allocation-free rule) ----------------
__device__ __align__(256) __nv_bfloat16 g_unitb[NROWS * DIM]; // 8 MB normalized bf16
__device__ float g_part[NT * NROWS];                          // per-(slot,row) partials
__device__ float g_pos[NROWS];
__device__ float g_blk[NT];

__device__ __forceinline__ uint32_t smem_u32(const void* p) {
    uint32_t a;
    asm("{ .reg .u64 t; cvta.to.shared.u64 t, %1; cvt.u32.u64 %0, t; }"
        : "=r"(a) : "l"(p));
    return a;
}

#define CP_ASYNC16(dst, src) \
    asm volatile("cp.async.cg.shared.global [%0], [%1], 16;" :: "r"(dst), "l"(src))
#define CP_COMMIT() asm volatile("cp.async.commit_group;" ::: "memory")
#define CP_WAIT0()  asm volatile("cp.async.wait_group 0;" ::: "memory")

#define LDMATRIX_X4(r0, r1, r2, r3, addr) \
    asm volatile("ldmatrix.sync.aligned.m8n8.x4.shared.b16 {%0,%1,%2,%3}, [%4];" \
                 : "=r"(r0), "=r"(r1), "=r"(r2), "=r"(r3) : "r"(addr))

#define MMA_BF16(c, a, b0, b1) \
    asm volatile("mma.sync.aligned.m16n8k16.row.col.f32.bf16.bf16.f32 " \
                 "{%0,%1,%2,%3}, {%4,%5,%6,%7}, {%8,%9}, {%0,%1,%2,%3};" \
                 : "+f"((c)[0]), "+f"((c)[1]), "+f"((c)[2]), "+f"((c)[3]) \
                 : "r"((a)[0]), "r"((a)[1]), "r"((a)[2]), "r"((a)[3]), \
                   "r"(b0), "r"(b1))

// ---------------------------------------------------------------------------
// 1) Normalize + bf16 convert: one block (128 threads) per row of concat(z1,z2)
// ---------------------------------------------------------------------------
__global__ __launch_bounds__(128)
void normalize_kernel(const float* __restrict__ z1, const float* __restrict__ z2) {
    int row = blockIdx.x;
    int t = threadIdx.x;
    const float* src = (row < HALF_N) ? (z1 + (size_t)row * DIM)
                                      : (z2 + (size_t)(row - HALF_N) * DIM);
    float v[4];
    float ss = 0.f;
#pragma unroll
    for (int i = 0; i < 4; i++) {
        v[i] = src[t + i * 128];
        ss += v[i] * v[i];
    }
#pragma unroll
    for (int o = 16; o > 0; o >>= 1) ss += __shfl_xor_sync(0xffffffffu, ss, o);
    __shared__ float ws[4];
    if ((t & 31) == 0) ws[t >> 5] = ss;
    __syncthreads();
    float tot = ws[0] + ws[1] + ws[2] + ws[3];
    float inv = 1.0f / fmaxf(sqrtf(tot), 1e-8f);
#pragma unroll
    for (int i = 0; i < 4; i++)
        g_unitb[(size_t)row * DIM + t + i * 128] = __float2bfloat16(v[i] * inv);
}

// ---------------------------------------------------------------------------
// 2) bf16 HMMA GEMM tile (128x128, K=512, BK=64, 2-stage cp.async),
//    upper-triangle tiles only via 1D triangular launch. Off-diagonal tiles
//    emit BOTH row-sum and col-sum partials (S = S^T).
//    8 warps: warp_m = wid&1 (2 x 64 rows), warp_n = wid>>1 (4 x 32 cols).
// ---------------------------------------------------------------------------
__device__ __forceinline__ void load_stage(uint32_t sbase,
                                           const __nv_bfloat16* __restrict__ g,
                                           int R0, int C0, int kk, int t) {
#pragma unroll
    for (int l = 0; l < 4; l++) {          // A tile: 128 rows x 8 chunks of 16B
        int idx = t + l * 256;
        int row = idx >> 3, c4 = idx & 7;
        uint32_t dst = sbase + (uint32_t)(row * PITCHB + c4 * 16);
        const void* src = g + (size_t)(R0 + row) * DIM + kk + c4 * 8;
        CP_ASYNC16(dst, src);
    }
#pragma unroll
    for (int l = 0; l < 4; l++) {          // B tile
        int idx = t + l * 256;
        int row = idx >> 3, c4 = idx & 7;
        uint32_t dst = sbase + (uint32_t)(TILE_B + row * PITCHB + c4 * 16);
        const void* src = g + (size_t)(C0 + row) * DIM + kk + c4 * 8;
        CP_ASYNC16(dst, src);
    }
}

__global__ __launch_bounds__(256, 2)
void gemm_exp_kernel() {
    // triangular decode: block b -> (bi, bj), bi <= bj, bi-major
    int b = blockIdx.x;
    float tf = (float)NT + 0.5f;
    int bi = (int)(tf - sqrtf(fmaxf(tf * tf - 2.0f * (float)b, 0.f)));
    while ((bi + 1) * NT - ((bi + 1) * bi) / 2 <= b) bi++;
    while (bi * NT - (bi * (bi - 1)) / 2 > b) bi--;
    int bj = bi + (b - (bi * NT - (bi * (bi - 1)) / 2));

    extern __shared__ __align__(128) char sm[];
    uint32_t sb = smem_u32(sm);

    int t = threadIdx.x;
    int lane = t & 31, wid = t >> 5;
    int warp_m = wid & 1, warp_n = wid >> 1;
    int R0 = bi * 128, C0 = bj * 128;
    bool offdiag = (bi != bj);

    float acc[4][4][4];
#pragma unroll
    for (int i = 0; i < 4; i++)
#pragma unroll
        for (int f = 0; f < 4; f++)
#pragma unroll
            for (int e = 0; e < 4; e++) acc[i][f][e] = 0.f;

    // fragment load address components (per thread, stage-relative)
    int a_row = warp_m * 64 + (lane & 7) + ((lane >> 3) & 1) * 8; // + i*16
    int a_col8 = (lane >> 4) * 8;                                 // + k0
    int b_row = warp_n * 32 + (lane & 7) + (lane >> 4) * 8;       // + nb*16
    int b_col8 = ((lane >> 3) & 1) * 8;                           // + k0

    load_stage(sb, g_unitb, R0, C0, 0, t);
    CP_COMMIT();

#pragma unroll 1
    for (int it = 0; it < 8; it++) {
        CP_WAIT0();
        __syncthreads();
        if (it < 7) {
            load_stage(sb + ((it + 1) & 1) * STAGE_B, g_unitb, R0, C0,
                       (it + 1) * BK, t);
            CP_COMMIT();
        }
        uint32_t ab = sb + (it & 1) * STAGE_B;
        uint32_t bb = ab + TILE_B;

#pragma unroll
        for (int ks = 0; ks < 4; ks++) {
            int k0 = ks * 16;
            uint32_t a[4][4], bfr[2][4];
#pragma unroll
            for (int i = 0; i < 4; i++) {
                uint32_t addr = ab + (uint32_t)((a_row + i * 16) * PITCHB +
                                                (a_col8 + k0) * 2);
                LDMATRIX_X4(a[i][0], a[i][1], a[i][2], a[i][3], addr);
            }
#pragma unroll
            for (int nb = 0; nb < 2; nb++) {
                uint32_t addr = bb + (uint32_t)((b_row + nb * 16) * PITCHB +
                                                (b_col8 + k0) * 2);
                LDMATRIX_X4(bfr[nb][0], bfr[nb][1], bfr[nb][2], bfr[nb][3], addr);
            }
#pragma unroll
            for (int i = 0; i < 4; i++)
#pragma unroll
                for (int f = 0; f < 4; f++)
                    MMA_BF16(acc[i][f], a[i], bfr[f >> 1][(f & 1) * 2],
                             bfr[f >> 1][(f & 1) * 2 + 1]);
        }
    }
    __syncthreads();   // all compute done; smem now reusable for reduction

    // Epilogue. C frag: reg e -> row (lane>>2) + 8*(e>>1), col 2*(lane&3)+(e&1)
    int g = lane >> 2, tq = lane & 3;
    float* red  = (float*)sm;                // 128 rows x 4 warp_n   (2 KB)
    float* redC = (float*)(sm + 2048);       // 128 cols x 2 warp_m   (1 KB)
    float rsum[4][2];
    float csum[4][2];
#pragma unroll
    for (int f = 0; f < 4; f++) { csum[f][0] = 0.f; csum[f][1] = 0.f; }

#pragma unroll
    for (int i = 0; i < 4; i++) {
#pragma unroll
        for (int h = 0; h < 2; h++) {
            int rg = R0 + warp_m * 64 + i * 16 + g + 8 * h;
            int pcol = (rg + HALF_N) & (NROWS - 1);
            float s = 0.f;
#pragma unroll
            for (int f = 0; f < 4; f++) {
#pragma unroll
                for (int e = 0; e < 2; e++) {
                    int cg = C0 + warp_n * 32 + f * 8 + tq * 2 + e;
                    float logit = acc[i][f][h * 2 + e] * 10.0f;
                    if (cg == pcol) {          // only occurs when bj == bi+32
                        g_pos[rg] = logit;     // unique writers (symmetric pair)
                        g_pos[cg] = logit;
                    }
                    float ev = (cg == rg) ? 0.f : __expf(logit);
                    s += ev;
                    csum[f][e] += ev;
                }
            }
            rsum[i][h] = s;
        }
    }
    // row-sum reduction over the 4 column-quads within each warp
#pragma unroll
    for (int i = 0; i < 4; i++)
#pragma unroll
        for (int h = 0; h < 2; h++) {
            float v = rsum[i][h];
            v += __shfl_xor_sync(0xffffffffu, v, 1);
            v += __shfl_xor_sync(0xffffffffu, v, 2);
            if (tq == 0)
                red[(warp_m * 64 + i * 16 + g + 8 * h) * 4 + warp_n] = v;
        }
    // col-sum reduction over the 8 row-groups within each warp
    if (offdiag) {
#pragma unroll
        for (int f = 0; f < 4; f++)
#pragma unroll
            for (int e = 0; e < 2; e++) {
                float v = csum[f][e];
                v += __shfl_xor_sync(0xffffffffu, v, 4);
                v += __shfl_xor_sync(0xffffffffu, v, 8);
                v += __shfl_xor_sync(0xffffffffu, v, 16);
                if (g == 0)
                    redC[(warp_n * 32 + f * 8 + tq * 2 + e) * 2 + warp_m] = v;
            }
    }
    __syncthreads();
    if (t < 128) {
        float s = red[t * 4] + red[t * 4 + 1] + red[t * 4 + 2] + red[t * 4 + 3];
        g_part[(size_t)bj * NROWS + R0 + t] = s;              // rows of tile bi
        if (offdiag)
            g_part[(size_t)bi * NROWS + C0 + t] = redC[t * 2] + redC[t * 2 + 1];
    }
}

// ---------------------------------------------------------------------------
// 3) Finalize (two deterministic stages; stage 1 block-reduces to 64 partials)
// ---------------------------------------------------------------------------
__global__ __launch_bounds__(128)
void finalize1_kernel() {
    int t = threadIdx.x;
    int r = blockIdx.x * 128 + t;
    float rs = 0.f;
#pragma unroll 8
    for (int c = 0; c < NT; c++) rs += g_part[(size_t)c * NROWS + r];
    float v = logf(rs) - g_pos[r];
#pragma unroll
    for (int o = 16; o > 0; o >>= 1) v += __shfl_xor_sync(0xffffffffu, v, o);
    __shared__ float ws[4];
    if ((t & 31) == 0) ws[t >> 5] = v;
    __syncthreads();
    if (t == 0) g_blk[blockIdx.x] = ws[0] + ws[1] + ws[2] + ws[3];
}

__global__ __launch_bounds__(32)
void finalize2_kernel(float* __restrict__ out) {
    int t = threadIdx.x;
    float sum = g_blk[t] + g_blk[t + 32];
#pragma unroll
    for (int o = 16; o > 0; o >>= 1) sum += __shfl_xor_sync(0xffffffffu, sum, o);
    if (t == 0) out[0] = sum / (float)NROWS;
}

extern "C" void kernel_launch(void* const* d_in, const int* in_sizes, int n_in,
                              void* d_out, int out_size) {
    const float* z1 = (const float*)d_in[0];
    const float* z2 = (const float*)d_in[1];

    static int configured = 0;
    if (!configured) {
        cudaFuncSetAttribute(gemm_exp_kernel,
                             cudaFuncAttributeMaxDynamicSharedMemorySize, SMEM_DYN);
        configured = 1;
    }

    normalize_kernel<<<NROWS, 128>>>(z1, z2);
    gemm_exp_kernel<<<NTRI, 256, SMEM_DYN>>>();
    finalize1_kernel<<<NT, 128>>>();
    finalize2_kernel<<<1, 32>>>((float*)d_out);
}